// round 13
// baseline (speedup 1.0000x reference)
#include <cuda_runtime.h>
#include <cstdint>

#define BB   32
#define NN   4096
#define CIN  128
#define COUT 128
#define MM   256
#define SPLITK_A 4

__device__ __forceinline__ float tf32r(float f) {
    uint32_t u;
    asm("cvt.rna.tf32.f32 %0, %1;" : "=r"(u) : "f"(f));
    return __uint_as_float(u);
}
__device__ __forceinline__ uint32_t tf32r_u(uint32_t v) {
    uint32_t r;
    asm("cvt.rna.tf32.f32 %0, %1;" : "=r"(r) : "f"(__uint_as_float(v)));
    return r;
}
__device__ __forceinline__ uint32_t smem_to_u32(const void* p) {
    uint32_t a;
    asm("{ .reg .u64 t; cvta.to.shared.u64 t, %1; cvt.u32.u64 %0, t; }" : "=r"(a) : "l"(p));
    return a;
}

// ===========================================================================
// Scratch (device globals — allocation-guard safe)
// ===========================================================================
__device__ __align__(16) float g_xsp[BB * SPLITK_A * MM * CIN];        // stage-A split-K partials
__device__ __align__(16) float g_xsum[MM * BB * CIN];                  // folded, [m][b][c], tf32
__device__ __align__(16) float g_wt[MM * CIN * COUT];                  // [m][c][o], tf32-rounded
__device__ __align__(16) float g_ospec[BB * MM * COUT];                // [b][m][o] tf32-rounded

// ===========================================================================
// kT: W_real[c][o][m] -> g_wt[m][c][o], tf32-rounded  (runs on side stream)
// ===========================================================================
__global__ __launch_bounds__(256) void kT(const float* __restrict__ W) {
    __shared__ float tile[32][33];
    const int c = blockIdx.x, o0 = blockIdx.y * 32, m0 = blockIdx.z * 32;
    const int tx = threadIdx.x, ty = threadIdx.y;
#pragma unroll
    for (int j = 0; j < 32; j += 8)
        tile[ty + j][tx] = W[((size_t)c * COUT + (o0 + ty + j)) * MM + m0 + tx];
    __syncthreads();
#pragma unroll
    for (int j = 0; j < 32; j += 8)
        g_wt[((size_t)(m0 + ty + j) * CIN + c) * COUT + o0 + tx] = tf32r(tile[tx][ty + j]);
}

// ===========================================================================
// tf32 GEMM (R8 config): CTA 128x128, 4 warps of 64x64, BK=32, double-buffered.
//   CVTA / CVTB: round A / B fragments to tf32(RN) in-register (raw fp32 src).
// ===========================================================================
template <bool ATRANS, bool CVTA, bool CVTB, int KCTA, int SPLITK>
__global__ __launch_bounds__(128, 2) void kGemm(
    const float* __restrict__ gA, const float* __restrict__ gB, float* __restrict__ gC,
    int lda, int ldb, int ldc, size_t strideB, size_t strideC)
{
    constexpr int ASZ = ATRANS ? 32 * 136 : 128 * 36;
    constexpr int BSZ = 32 * 136;
    constexpr int BUFST = ASZ + BSZ;
    extern __shared__ float sm[];
    const uint32_t smU = smem_to_u32(sm);

    const int tid = threadIdx.x;
    const int w = tid >> 5, lane = tid & 31;
    const int m_w = (w & 1) * 64, j_w = (w >> 1) * 64;
    const int r4 = lane >> 2, c4 = lane & 3;

    const int i0 = blockIdx.x * 128;
    const int z  = blockIdx.z;
    const int b  = z / SPLITK;
    const int kbase = (z - b * SPLITK) * KCTA;
    const float* gBb = gB + (size_t)b * strideB;

    float acc[4][8][4];
#pragma unroll
    for (int mt = 0; mt < 4; mt++)
#pragma unroll
        for (int nt = 0; nt < 8; nt++)
#pragma unroll
            for (int q = 0; q < 4; q++) acc[mt][nt][q] = 0.f;

    auto load = [&](int k0, int buf) {
        uint32_t aU = smU + (uint32_t)(buf * BUFST) * 4u;
        uint32_t bU = aU + (uint32_t)ASZ * 4u;
#pragma unroll
        for (int it = 0; it < 8; it++) {
            int t4 = tid + it * 128;
            const float* src; uint32_t so;
            if (ATRANS) {
                int kr = t4 >> 5, cc = (t4 & 31) * 4;
                src = gA + (size_t)(k0 + kr) * lda + i0 + cc;
                so = (uint32_t)(kr * 136 + cc);
            } else {
                int rr = t4 >> 3, cc = (t4 & 7) * 4;
                src = gA + (size_t)(i0 + rr) * lda + k0 + cc;
                so = (uint32_t)(rr * 36 + cc);
            }
            asm volatile("cp.async.cg.shared.global [%0], [%1], 16;" :: "r"(aU + so * 4u), "l"(src));
        }
#pragma unroll
        for (int it = 0; it < 8; it++) {
            int t4 = tid + it * 128;
            int kr = t4 >> 5, cc = (t4 & 31) * 4;
            const float* src = gBb + (size_t)(k0 + kr) * ldb + cc;
            asm volatile("cp.async.cg.shared.global [%0], [%1], 16;"
                         :: "r"(bU + (uint32_t)(kr * 136 + cc) * 4u), "l"(src));
        }
        asm volatile("cp.async.commit_group;");
    };

    load(kbase, 0);
    constexpr int NCH = KCTA / 32;
    for (int ch = 0; ch < NCH; ch++) {
        const int buf = ch & 1;
        if (ch + 1 < NCH) {
            load(kbase + (ch + 1) * 32, buf ^ 1);
            asm volatile("cp.async.wait_group 1;");
        } else {
            asm volatile("cp.async.wait_group 0;");
        }
        __syncthreads();

        const float* as = sm + buf * BUFST;
        const float* bs = as + ASZ;
#pragma unroll
        for (int kk = 0; kk < 32; kk += 8) {
            uint32_t a[4][4], bf[8][2];
#pragma unroll
            for (int mt = 0; mt < 4; mt++) {
                const int ib = m_w + mt * 16 + r4;
                if (ATRANS) {
                    const float* p0 = as + (kk + c4) * 136 + ib;
                    a[mt][0] = __float_as_uint(p0[0]);
                    a[mt][1] = __float_as_uint(p0[8]);
                    a[mt][2] = __float_as_uint(p0[4 * 136]);
                    a[mt][3] = __float_as_uint(p0[4 * 136 + 8]);
                } else {
                    const float* p0 = as + ib * 36 + kk + c4;
                    a[mt][0] = __float_as_uint(p0[0]);
                    a[mt][1] = __float_as_uint(p0[8 * 36]);
                    a[mt][2] = __float_as_uint(p0[4]);
                    a[mt][3] = __float_as_uint(p0[8 * 36 + 4]);
                }
                if (CVTA) {
                    a[mt][0] = tf32r_u(a[mt][0]);
                    a[mt][1] = tf32r_u(a[mt][1]);
                    a[mt][2] = tf32r_u(a[mt][2]);
                    a[mt][3] = tf32r_u(a[mt][3]);
                }
            }
#pragma unroll
            for (int nt = 0; nt < 8; nt++) {
                const float* pb = bs + (kk + c4) * 136 + j_w + nt * 8 + r4;
                uint32_t b0 = __float_as_uint(pb[0]);
                uint32_t b1 = __float_as_uint(pb[4 * 136]);
                if (CVTB) { b0 = tf32r_u(b0); b1 = tf32r_u(b1); }
                bf[nt][0] = b0; bf[nt][1] = b1;
            }
#pragma unroll
            for (int mt = 0; mt < 4; mt++)
#pragma unroll
                for (int nt = 0; nt < 8; nt++)
                    asm volatile(
                        "mma.sync.aligned.m16n8k8.row.col.f32.tf32.tf32.f32 "
                        "{%0,%1,%2,%3}, {%4,%5,%6,%7}, {%8,%9}, {%0,%1,%2,%3};"
                        : "+f"(acc[mt][nt][0]), "+f"(acc[mt][nt][1]),
                          "+f"(acc[mt][nt][2]), "+f"(acc[mt][nt][3])
                        : "r"(a[mt][0]), "r"(a[mt][1]), "r"(a[mt][2]), "r"(a[mt][3]),
                          "r"(bf[nt][0]), "r"(bf[nt][1]));
        }
        __syncthreads();
    }

    float* cb = gC + (size_t)z * strideC;
#pragma unroll
    for (int mt = 0; mt < 4; mt++)
#pragma unroll
        for (int nt = 0; nt < 8; nt++) {
            const int r = i0 + m_w + mt * 16 + r4;
            const int c = j_w + nt * 8 + c4 * 2;
            float2 v0 = { acc[mt][nt][0], acc[mt][nt][1] };
            float2 v1 = { acc[mt][nt][2], acc[mt][nt][3] };
            *(float2*)&cb[(size_t)r * ldc + c] = v0;
            *(float2*)&cb[(size_t)(r + 8) * ldc + c] = v1;
        }
}

// ===========================================================================
// kFold v2: g_xsum[m][b][c] = tf32(sum_s xsp[b][s][m][c])  — no transpose,
// float4 streaming both sides. Grid 1024 x 256 threads, 1 float4/thread.
// ===========================================================================
__global__ __launch_bounds__(256) void kFold() {
    const int id = blockIdx.x * 256 + threadIdx.x;   // 0..262143
    const int m  = id >> 10;
    const int rem = id & 1023;
    const int b  = rem >> 5;
    const int cg = (rem & 31) * 4;

    const float* base = g_xsp + (((size_t)b * SPLITK_A) * MM + m) * CIN + cg;
    float4 v = *(const float4*)base;
#pragma unroll
    for (int s = 1; s < SPLITK_A; s++) {
        float4 p = *(const float4*)(base + (size_t)s * MM * CIN);
        v.x += p.x; v.y += p.y; v.z += p.z; v.w += p.w;
    }
    v.x = tf32r(v.x); v.y = tf32r(v.y); v.z = tf32r(v.z); v.w = tf32r(v.w);
    *(float4*)&g_xsum[(((size_t)m * BB) + b) * CIN + cg] = v;
}

// ===========================================================================
// Stage B (tensor): ospec[b][m][o] = sum_c xsum[m][b][c] * wt[m][c][o]
//   A operand row-major [b][c] (pad 132), W half [c][o] (pad 72), both via
//   ONE cp.async group. Grid (m, o-half) = 512 CTAs, 8 warps: 2(b) x 4(o).
// ===========================================================================
#define B3_XPAD 132
#define B3_WPAD 72
#define B3_XSZ (BB * B3_XPAD)                   // 4224 floats
#define SMEM_B3 ((B3_XSZ + CIN * B3_WPAD) * 4)  // 53760 B

__global__ __launch_bounds__(256) void kB3() {
    extern __shared__ float smB[];
    float* xs = smB;                  // [b][c] pad 132
    float* Ws = smB + B3_XSZ;         // [c][o] pad 72
    const uint32_t xsU = smem_to_u32(xs);
    const uint32_t wsU = smem_to_u32(Ws);

    const int m = blockIdx.x;
    const int h = blockIdx.y;
    const int t = threadIdx.x;
    const int w = t >> 5, lane = t & 31;
    const int r4 = lane >> 2, c4 = lane & 3;
    const int m_w = (w & 1) * 16;       // b-offset of warp
    const int j_w = (w >> 1) * 16;      // o-offset of warp

    // --- cp.async xsum slice: 32 b-rows x 128 c floats (512B rows) ---
    const float* xm = g_xsum + (size_t)m * BB * CIN;
#pragma unroll
    for (int it = 0; it < 4; it++) {
        int t4 = t + it * 256;          // 0..1023 (16B chunks)
        int br = t4 >> 5;               // 0..31
        int cc = (t4 & 31) * 4;         // 0..124
        asm volatile("cp.async.cg.shared.global [%0], [%1], 16;"
                     :: "r"(xsU + (uint32_t)((br * B3_XPAD + cc) * 4)),
                        "l"(xm + (size_t)br * CIN + cc));
    }
    // --- cp.async W half: 128 c-rows x 64 o floats ---
    const float* wtm = g_wt + (size_t)m * CIN * COUT + h * 64;
#pragma unroll
    for (int it = 0; it < 8; it++) {
        int t4 = t + it * 256;          // 0..2047
        int cr = t4 >> 4;               // 0..127
        int oc = (t4 & 15) * 4;         // 0..60
        asm volatile("cp.async.cg.shared.global [%0], [%1], 16;"
                     :: "r"(wsU + (uint32_t)((cr * B3_WPAD + oc) * 4)),
                        "l"(wtm + (size_t)cr * COUT + oc));
    }
    asm volatile("cp.async.commit_group;");
    asm volatile("cp.async.wait_group 0;");
    __syncthreads();

    float acc[2][4];
#pragma unroll
    for (int nt = 0; nt < 2; nt++)
#pragma unroll
        for (int q = 0; q < 4; q++) acc[nt][q] = 0.f;

#pragma unroll
    for (int kk = 0; kk < CIN; kk += 8) {
        const float* pa = xs + (m_w + r4) * B3_XPAD + kk + c4;
        uint32_t a0 = __float_as_uint(pa[0]);
        uint32_t a1 = __float_as_uint(pa[8 * B3_XPAD]);
        uint32_t a2 = __float_as_uint(pa[4]);
        uint32_t a3 = __float_as_uint(pa[8 * B3_XPAD + 4]);
#pragma unroll
        for (int nt = 0; nt < 2; nt++) {
            const float* pb = Ws + (kk + c4) * B3_WPAD + j_w + nt * 8 + r4;
            uint32_t b0 = __float_as_uint(pb[0]);
            uint32_t b1 = __float_as_uint(pb[4 * B3_WPAD]);
            asm volatile(
                "mma.sync.aligned.m16n8k8.row.col.f32.tf32.tf32.f32 "
                "{%0,%1,%2,%3}, {%4,%5,%6,%7}, {%8,%9}, {%0,%1,%2,%3};"
                : "+f"(acc[nt][0]), "+f"(acc[nt][1]), "+f"(acc[nt][2]), "+f"(acc[nt][3])
                : "r"(a0), "r"(a1), "r"(a2), "r"(a3), "r"(b0), "r"(b1));
        }
    }

    // --- epilogue: ospec[b][m][o], tf32-rounded for stage C ---
#pragma unroll
    for (int nt = 0; nt < 2; nt++) {
        const int o = h * 64 + j_w + nt * 8 + c4 * 2;
        const int b0r = m_w + r4;
        float2 v0 = { tf32r(acc[nt][0]), tf32r(acc[nt][1]) };
        float2 v1 = { tf32r(acc[nt][2]), tf32r(acc[nt][3]) };
        *(float2*)&g_ospec[((size_t)b0r * MM + m) * COUT + o] = v0;
        *(float2*)&g_ospec[((size_t)(b0r + 8) * MM + m) * COUT + o] = v1;
    }
}

// ===========================================================================
// Launch — kT runs on a side stream concurrent with stage A (fork/join via
// events; stream+events created once on the uncaptured correctness call).
// ===========================================================================
static constexpr int SMEM_GA = 2 * (32 * 136 + 32 * 136) * 4;    // 69632 B
static constexpr int SMEM_GC = 2 * (128 * 36 + 32 * 136) * 4;    // 71680 B

extern "C" void kernel_launch(void* const* d_in, const int* in_sizes, int n_in,
                              void* d_out, int out_size) {
    const float* x = (const float*)d_in[0];   // [32,4096,128]
    const float* U = (const float*)d_in[1];   // [4096,256]
    const float* W = (const float*)d_in[2];   // [128,128,256] (W_imag d_in[3] is dead)
    float* out = (float*)d_out;               // [32,4096,128]

    float* dxsp; cudaGetSymbolAddress((void**)&dxsp, g_xsp);
    float* dos;  cudaGetSymbolAddress((void**)&dos,  g_ospec);

    cudaFuncSetAttribute((const void*)kGemm<true,  true, true,  NN / SPLITK_A, SPLITK_A>,
                         cudaFuncAttributeMaxDynamicSharedMemorySize, SMEM_GA);
    cudaFuncSetAttribute((const void*)kGemm<false, true, false, MM, 1>,
                         cudaFuncAttributeMaxDynamicSharedMemorySize, SMEM_GC);
    cudaFuncSetAttribute((const void*)kB3,
                         cudaFuncAttributeMaxDynamicSharedMemorySize, SMEM_B3);

    static cudaStream_t s1 = nullptr;
    static cudaEvent_t eFork = nullptr, eT = nullptr;
    if (s1 == nullptr) {
        cudaStreamCreateWithFlags(&s1, cudaStreamNonBlocking);
        cudaEventCreateWithFlags(&eFork, cudaEventDisableTiming);
        cudaEventCreateWithFlags(&eT, cudaEventDisableTiming);
    }

    // Fork: kT on s1, concurrent with stage A on the main stream.
    cudaEventRecord(eFork, 0);
    cudaStreamWaitEvent(s1, eFork, 0);
    kT<<<dim3(CIN, COUT / 32, MM / 32), dim3(32, 8), 0, s1>>>(W);
    cudaEventRecord(eT, s1);

    // Stage A: xsp[b][s][m][c] partials = sum_{n slice} U[n][m] * x[b][n][c]
    //   A = raw U (CVTA), B = raw x (CVTB). Grid 2 x 1 x 128 = 256 CTAs.
    kGemm<true, true, true, NN / SPLITK_A, SPLITK_A>
        <<<dim3(MM / 128, 1, BB * SPLITK_A), 128, SMEM_GA>>>(
            U, x, dxsp, MM, CIN, CIN, (size_t)NN * CIN, (size_t)MM * CIN);

    // Fold split-K partials (pure float4 streaming, no transpose)
    kFold<<<1024, 256>>>();

    // Join: kB3 needs g_wt from kT.
    cudaStreamWaitEvent(0, eT, 0);

    // Stage B: per-mode channel mix on tensor pipe (fully async operands)
    kB3<<<dim3(MM, 2), 256, SMEM_B3>>>();

    // Stage C: out[b][n][o] = sum_m U[n][m] * ospec[b][m][o]
    //   A = raw U (CVTA), B = ospec pre-rounded.
    kGemm<false, true, false, MM, 1>
        <<<dim3(NN / 128, 1, BB), 128, SMEM_GC>>>(
            U, dos, out, MM, COUT, COUT, (size_t)MM * COUT, (size_t)NN * COUT);
}

// round 14
// speedup vs baseline: 1.2648x; 1.2648x over previous
#include <cuda_runtime.h>
#include <cuda_fp16.h>
#include <cstdint>

#define BB   32
#define NN   4096
#define CIN  128
#define COUT 128
#define MM   256
#define SPLITK_A 4

__device__ __forceinline__ float tf32r(float f) {
    uint32_t u;
    asm("cvt.rna.tf32.f32 %0, %1;" : "=r"(u) : "f"(f));
    return __uint_as_float(u);
}
__device__ __forceinline__ uint32_t packh2(float lo, float hi) {
    uint32_t r;
    asm("cvt.rn.f16x2.f32 %0, %1, %2;" : "=r"(r) : "f"(hi), "f"(lo));
    return r;
}
__device__ __forceinline__ uint32_t smem_to_u32(const void* p) {
    uint32_t a;
    asm("{ .reg .u64 t; cvta.to.shared.u64 t, %1; cvt.u32.u64 %0, t; }" : "=r"(a) : "l"(p));
    return a;
}

// ===========================================================================
// Scratch (device globals — allocation-guard safe)
// ===========================================================================
__device__ __align__(16) __half g_Uh[NN * MM];                   // fp16 U  [n][m]
__device__ __align__(16) __half g_Uth[MM * NN];                  // fp16 U^T [m][n]
__device__ __align__(16) float g_xsp[BB * SPLITK_A * MM * CIN];  // stage-A split-K partials
__device__ __align__(16) float g_xsum[MM * BB * CIN];            // folded, [m][b][c], tf32
__device__ __align__(16) float g_wt[MM * CIN * COUT];            // [m][c][o], tf32-rounded
__device__ __align__(16) float g_ospec[BB * MM * COUT];          // [b][m][o] tf32-rounded

// ===========================================================================
// kPrepU: U [n][m] fp32 -> g_Uh [n][m] fp16 and g_Uth [m][n] fp16
// ===========================================================================
__global__ __launch_bounds__(256) void kPrepU(const float* __restrict__ U) {
    __shared__ float t[32][33];
    const int n0 = blockIdx.x * 32, m0 = blockIdx.y * 32;
    const int tx = threadIdx.x, ty = threadIdx.y;
#pragma unroll
    for (int j = 0; j < 32; j += 8) {
        float v = U[(size_t)(n0 + ty + j) * MM + m0 + tx];
        t[ty + j][tx] = v;
        g_Uh[(size_t)(n0 + ty + j) * MM + m0 + tx] = __float2half_rn(v);
    }
    __syncthreads();
#pragma unroll
    for (int j = 0; j < 32; j += 8)
        g_Uth[(size_t)(m0 + ty + j) * NN + n0 + tx] = __float2half_rn(t[tx][ty + j]);
}

// ===========================================================================
// kT: W_real[c][o][m] -> g_wt[m][c][o], tf32-rounded  (side stream)
// ===========================================================================
__global__ __launch_bounds__(256) void kT(const float* __restrict__ W) {
    __shared__ float tile[32][33];
    const int c = blockIdx.x, o0 = blockIdx.y * 32, m0 = blockIdx.z * 32;
    const int tx = threadIdx.x, ty = threadIdx.y;
#pragma unroll
    for (int j = 0; j < 32; j += 8)
        tile[ty + j][tx] = W[((size_t)c * COUT + (o0 + ty + j)) * MM + m0 + tx];
    __syncthreads();
#pragma unroll
    for (int j = 0; j < 32; j += 8)
        g_wt[((size_t)(m0 + ty + j) * CIN + c) * COUT + o0 + tx] = tf32r(tile[tx][ty + j]);
}

// ===========================================================================
// fp16 GEMM: CTA 128(i) x 128(j), 4 warps of 64x64, BK=32, double-buffered.
//   A: fp16, row-major [i][k] (pre-converted U / U^T), pad 40 halves/row.
//   B: fp32 [k][n] (pad 132), packed to half2 in-register (RN) per fragment.
//   mma.m16n8k16.row.col.f32.f16.f16.f32, fp32 accum.
// ===========================================================================
#define A_BYTES (128 * 40 * 2)          // 10240
#define B_BYTES (32 * 132 * 4)          // 16896
#define BUF_BYTES (A_BYTES + B_BYTES)   // 27136
#define SMEM_G (2 * BUF_BYTES)          // 54272

template <int KCTA, int SPLITK>
__global__ __launch_bounds__(128, 2) void kGemmH(
    const __half* __restrict__ gA, const float* __restrict__ gB, float* __restrict__ gC,
    int lda, int ldb, int ldc, size_t strideB, size_t strideC)
{
    extern __shared__ char smc[];
    const uint32_t smU = smem_to_u32(smc);

    const int tid = threadIdx.x;
    const int w = tid >> 5, lane = tid & 31;
    const int m_w = (w & 1) * 64, j_w = (w >> 1) * 64;
    const int r4 = lane >> 2, c4 = lane & 3;

    const int i0 = blockIdx.x * 128;
    const int z  = blockIdx.z;
    const int b  = z / SPLITK;
    const int kbase = (z - b * SPLITK) * KCTA;
    const float* gBb = gB + (size_t)b * strideB;

    float acc[4][8][4];
#pragma unroll
    for (int mt = 0; mt < 4; mt++)
#pragma unroll
        for (int nt = 0; nt < 8; nt++)
#pragma unroll
            for (int q = 0; q < 4; q++) acc[mt][nt][q] = 0.f;

    auto load = [&](int k0, int buf) {
        const uint32_t base = smU + (uint32_t)(buf * BUF_BYTES);
        // A: 128 rows x 32 halves (64B) = 512 x 16B chunks
#pragma unroll
        for (int it = 0; it < 4; it++) {
            int t4 = tid + it * 128;
            int rr = t4 >> 2, cc = t4 & 3;
            const __half* src = gA + (size_t)(i0 + rr) * lda + k0 + cc * 8;
            asm volatile("cp.async.cg.shared.global [%0], [%1], 16;"
                         :: "r"(base + (uint32_t)(rr * 80 + cc * 16)), "l"(src));
        }
        // B: 32 rows x 128 floats (512B) = 1024 x 16B chunks
#pragma unroll
        for (int it = 0; it < 8; it++) {
            int t4 = tid + it * 128;
            int kr = t4 >> 5, cc = t4 & 31;
            const float* src = gBb + (size_t)(k0 + kr) * ldb + cc * 4;
            asm volatile("cp.async.cg.shared.global [%0], [%1], 16;"
                         :: "r"(base + (uint32_t)(A_BYTES + kr * 528 + cc * 16)), "l"(src));
        }
        asm volatile("cp.async.commit_group;");
    };

    load(kbase, 0);
    constexpr int NCH = KCTA / 32;
    for (int ch = 0; ch < NCH; ch++) {
        const int buf = ch & 1;
        if (ch + 1 < NCH) {
            load(kbase + (ch + 1) * 32, buf ^ 1);
            asm volatile("cp.async.wait_group 1;");
        } else {
            asm volatile("cp.async.wait_group 0;");
        }
        __syncthreads();

        const char*  as = smc + buf * BUF_BYTES;
        const float* bs = (const float*)(as + A_BYTES);
#pragma unroll
        for (int kk = 0; kk < 32; kk += 16) {
            uint32_t a[4][4], bf[8][2];
#pragma unroll
            for (int mt = 0; mt < 4; mt++) {
                const int i = m_w + mt * 16 + r4;
                const int hbase = i * 40 + kk + 2 * c4;     // half index (even)
                a[mt][0] = *(const uint32_t*)(as + (size_t)hbase * 2);
                a[mt][1] = *(const uint32_t*)(as + (size_t)(hbase + 320) * 2); // row +8
                a[mt][2] = *(const uint32_t*)(as + (size_t)(hbase + 8) * 2);   // k +8
                a[mt][3] = *(const uint32_t*)(as + (size_t)(hbase + 328) * 2);
            }
#pragma unroll
            for (int nt = 0; nt < 8; nt++) {
                const int n = j_w + nt * 8 + r4;
                const float* p0 = bs + (kk + 2 * c4) * 132 + n;
                bf[nt][0] = packh2(p0[0],        p0[132]);        // k, k+1
                bf[nt][1] = packh2(p0[8 * 132],  p0[9 * 132]);    // k+8, k+9
            }
#pragma unroll
            for (int mt = 0; mt < 4; mt++)
#pragma unroll
                for (int nt = 0; nt < 8; nt++)
                    asm volatile(
                        "mma.sync.aligned.m16n8k16.row.col.f32.f16.f16.f32 "
                        "{%0,%1,%2,%3}, {%4,%5,%6,%7}, {%8,%9}, {%0,%1,%2,%3};"
                        : "+f"(acc[mt][nt][0]), "+f"(acc[mt][nt][1]),
                          "+f"(acc[mt][nt][2]), "+f"(acc[mt][nt][3])
                        : "r"(a[mt][0]), "r"(a[mt][1]), "r"(a[mt][2]), "r"(a[mt][3]),
                          "r"(bf[nt][0]), "r"(bf[nt][1]));
        }
        __syncthreads();
    }

    float* cb = gC + (size_t)z * strideC;
#pragma unroll
    for (int mt = 0; mt < 4; mt++)
#pragma unroll
        for (int nt = 0; nt < 8; nt++) {
            const int r = i0 + m_w + mt * 16 + r4;
            const int c = j_w + nt * 8 + c4 * 2;
            float2 v0 = { acc[mt][nt][0], acc[mt][nt][1] };
            float2 v1 = { acc[mt][nt][2], acc[mt][nt][3] };
            *(float2*)&cb[(size_t)r * ldc + c] = v0;
            *(float2*)&cb[(size_t)(r + 8) * ldc + c] = v1;
        }
}

// ===========================================================================
// kFold: g_xsum[m][b][c] = tf32(sum_s xsp[b][s][m][c]) — float4 streaming
// ===========================================================================
__global__ __launch_bounds__(256) void kFold() {
    const int id = blockIdx.x * 256 + threadIdx.x;
    const int m  = id >> 10;
    const int rem = id & 1023;
    const int b  = rem >> 5;
    const int cg = (rem & 31) * 4;

    const float* base = g_xsp + (((size_t)b * SPLITK_A) * MM + m) * CIN + cg;
    float4 v = *(const float4*)base;
#pragma unroll
    for (int s = 1; s < SPLITK_A; s++) {
        float4 p = *(const float4*)(base + (size_t)s * MM * CIN);
        v.x += p.x; v.y += p.y; v.z += p.z; v.w += p.w;
    }
    v.x = tf32r(v.x); v.y = tf32r(v.y); v.z = tf32r(v.z); v.w = tf32r(v.w);
    *(float4*)&g_xsum[(((size_t)m * BB) + b) * CIN + cg] = v;
}

// ===========================================================================
// Stage B (tf32 tensor, unchanged from R13): ospec = xsum @ wt per mode
// ===========================================================================
#define B3_XPAD 132
#define B3_WPAD 72
#define B3_XSZ (BB * B3_XPAD)
#define SMEM_B3 ((B3_XSZ + CIN * B3_WPAD) * 4)

__global__ __launch_bounds__(256) void kB3() {
    extern __shared__ float smB[];
    float* xs = smB;
    float* Ws = smB + B3_XSZ;
    const uint32_t xsU = smem_to_u32(xs);
    const uint32_t wsU = smem_to_u32(Ws);

    const int m = blockIdx.x;
    const int h = blockIdx.y;
    const int t = threadIdx.x;
    const int w = t >> 5, lane = t & 31;
    const int r4 = lane >> 2, c4 = lane & 3;
    const int m_w = (w & 1) * 16;
    const int j_w = (w >> 1) * 16;

    const float* xm = g_xsum + (size_t)m * BB * CIN;
#pragma unroll
    for (int it = 0; it < 4; it++) {
        int t4 = t + it * 256;
        int br = t4 >> 5;
        int cc = (t4 & 31) * 4;
        asm volatile("cp.async.cg.shared.global [%0], [%1], 16;"
                     :: "r"(xsU + (uint32_t)((br * B3_XPAD + cc) * 4)),
                        "l"(xm + (size_t)br * CIN + cc));
    }
    const float* wtm = g_wt + (size_t)m * CIN * COUT + h * 64;
#pragma unroll
    for (int it = 0; it < 8; it++) {
        int t4 = t + it * 256;
        int cr = t4 >> 4;
        int oc = (t4 & 15) * 4;
        asm volatile("cp.async.cg.shared.global [%0], [%1], 16;"
                     :: "r"(wsU + (uint32_t)((cr * B3_WPAD + oc) * 4)),
                        "l"(wtm + (size_t)cr * COUT + oc));
    }
    asm volatile("cp.async.commit_group;");
    asm volatile("cp.async.wait_group 0;");
    __syncthreads();

    float acc[2][4];
#pragma unroll
    for (int nt = 0; nt < 2; nt++)
#pragma unroll
        for (int q = 0; q < 4; q++) acc[nt][q] = 0.f;

#pragma unroll
    for (int kk = 0; kk < CIN; kk += 8) {
        const float* pa = xs + (m_w + r4) * B3_XPAD + kk + c4;
        uint32_t a0 = __float_as_uint(pa[0]);
        uint32_t a1 = __float_as_uint(pa[8 * B3_XPAD]);
        uint32_t a2 = __float_as_uint(pa[4]);
        uint32_t a3 = __float_as_uint(pa[8 * B3_XPAD + 4]);
#pragma unroll
        for (int nt = 0; nt < 2; nt++) {
            const float* pb = Ws + (kk + c4) * B3_WPAD + j_w + nt * 8 + r4;
            uint32_t b0 = __float_as_uint(pb[0]);
            uint32_t b1 = __float_as_uint(pb[4 * B3_WPAD]);
            asm volatile(
                "mma.sync.aligned.m16n8k8.row.col.f32.tf32.tf32.f32 "
                "{%0,%1,%2,%3}, {%4,%5,%6,%7}, {%8,%9}, {%0,%1,%2,%3};"
                : "+f"(acc[nt][0]), "+f"(acc[nt][1]), "+f"(acc[nt][2]), "+f"(acc[nt][3])
                : "r"(a0), "r"(a1), "r"(a2), "r"(a3), "r"(b0), "r"(b1));
        }
    }

#pragma unroll
    for (int nt = 0; nt < 2; nt++) {
        const int o = h * 64 + j_w + nt * 8 + c4 * 2;
        const int b0r = m_w + r4;
        float2 v0 = { tf32r(acc[nt][0]), tf32r(acc[nt][1]) };
        float2 v1 = { tf32r(acc[nt][2]), tf32r(acc[nt][3]) };
        *(float2*)&g_ospec[((size_t)b0r * MM + m) * COUT + o] = v0;
        *(float2*)&g_ospec[((size_t)(b0r + 8) * MM + m) * COUT + o] = v1;
    }
}

// ===========================================================================
// Launch — kT on side stream concurrent with prepU + stage A.
// ===========================================================================
extern "C" void kernel_launch(void* const* d_in, const int* in_sizes, int n_in,
                              void* d_out, int out_size) {
    const float* x = (const float*)d_in[0];   // [32,4096,128]
    const float* U = (const float*)d_in[1];   // [4096,256]
    const float* W = (const float*)d_in[2];   // [128,128,256] (W_imag d_in[3] is dead)
    float* out = (float*)d_out;               // [32,4096,128]

    float* dxsp; cudaGetSymbolAddress((void**)&dxsp, g_xsp);
    float* dos;  cudaGetSymbolAddress((void**)&dos,  g_ospec);
    __half* dUh;  cudaGetSymbolAddress((void**)&dUh,  g_Uh);
    __half* dUth; cudaGetSymbolAddress((void**)&dUth, g_Uth);

    cudaFuncSetAttribute((const void*)kGemmH<NN / SPLITK_A, SPLITK_A>,
                         cudaFuncAttributeMaxDynamicSharedMemorySize, SMEM_G);
    cudaFuncSetAttribute((const void*)kGemmH<MM, 1>,
                         cudaFuncAttributeMaxDynamicSharedMemorySize, SMEM_G);
    cudaFuncSetAttribute((const void*)kB3,
                         cudaFuncAttributeMaxDynamicSharedMemorySize, SMEM_B3);

    static cudaStream_t s1 = nullptr;
    static cudaEvent_t eFork = nullptr, eT = nullptr;
    if (s1 == nullptr) {
        cudaStreamCreateWithFlags(&s1, cudaStreamNonBlocking);
        cudaEventCreateWithFlags(&eFork, cudaEventDisableTiming);
        cudaEventCreateWithFlags(&eT, cudaEventDisableTiming);
    }

    // Fork: kT on s1, concurrent with prepU + stage A on the main stream.
    cudaEventRecord(eFork, 0);
    cudaStreamWaitEvent(s1, eFork, 0);
    kT<<<dim3(CIN, COUT / 32, MM / 32), dim3(32, 8), 0, s1>>>(W);
    cudaEventRecord(eT, s1);

    // U -> fp16 (straight + transposed)
    kPrepU<<<dim3(NN / 32, MM / 32), dim3(32, 8)>>>(U);

    // Stage A: xsp partials = U^T @ x per batch-slice.  A = g_Uth [m][n] fp16.
    kGemmH<NN / SPLITK_A, SPLITK_A>
        <<<dim3(MM / 128, 1, BB * SPLITK_A), 128, SMEM_G>>>(
            dUth, x, dxsp, NN, CIN, CIN, (size_t)NN * CIN, (size_t)MM * CIN);

    // Fold split-K partials
    kFold<<<1024, 256>>>();

    // Join: kB3 needs g_wt from kT.
    cudaStreamWaitEvent(0, eT, 0);

    // Stage B: per-mode channel mix (tf32 tensor)
    kB3<<<dim3(MM, 2), 256, SMEM_B3>>>();

    // Stage C: out = U @ ospec per batch.  A = g_Uh [n][m] fp16.
    kGemmH<MM, 1>
        <<<dim3(NN / 128, 1, BB), 128, SMEM_G>>>(
            dUh, dos, out, MM, COUT, COUT, (size_t)MM * COUT, (size_t)NN * COUT);
}